// round 2
// baseline (speedup 1.0000x reference)
#include <cuda_runtime.h>
#include <cuda_bf16.h>
#include <math_constants.h>

// Problem dims (fixed by the dataset)
#define BB 4096   // batch
#define DD 128    // feature dim
#define KV 4096   // num keys
#define EE 1024   // embed
#define HH 2048   // hidden
#define VV 64     // value dim

// ---------------------------------------------------------------------------
// Scratch (device globals -- no allocation allowed in kernel_launch)
// ---------------------------------------------------------------------------
__device__ float g_s[(size_t)BB * KV];   // diff -> score s           (64 MB)
__device__ float g_e[(size_t)BB * EE];   // embed activations         (16 MB)
__device__ float g_h[(size_t)BB * HH];   // hidden activations        (32 MB)
__device__ float g_l[(size_t)BB * KV];   // logits -> att             (64 MB)
__device__ float g_x2[BB];
__device__ float g_k2[KV];

// ---------------------------------------------------------------------------
// Row squared-norm: one block (128 threads) per row, D = 128
// ---------------------------------------------------------------------------
__global__ void rownorm2_kernel(const float* __restrict__ X, float* __restrict__ out)
{
    int row = blockIdx.x;
    float v = X[(size_t)row * DD + threadIdx.x];
    float s = v * v;
    #pragma unroll
    for (int o = 16; o > 0; o >>= 1) s += __shfl_down_sync(0xffffffffu, s, o);
    __shared__ float ws[4];
    if ((threadIdx.x & 31) == 0) ws[threadIdx.x >> 5] = s;
    __syncthreads();
    if (threadIdx.x == 0) out[row] = ws[0] + ws[1] + ws[2] + ws[3];
}

// ---------------------------------------------------------------------------
// Tiled fp32 GEMM, 128x128 tile, BK=8, 256 threads, 8x8 per thread,
// register->smem DOUBLE-BUFFERED mainloop (1 __syncthreads per k-step).
//   TRANSB = false : C[M,N] = A[M,Kd] * Bm[Kd,N]      (both row-major)
//   TRANSB = true  : C[M,N] = A[M,Kd] * Bm[N,Kd]^T    (NT; inner dim contiguous)
// EPI: 0 = none, 1 = +bias, 2 = relu(+bias), 3 = dist: sqrt(max(rv+cv-2acc,0))
// M, N multiples of 128; Kd multiple of 8 and >= 16.
// ---------------------------------------------------------------------------
template<int EPI, bool TRANSB>
__global__ __launch_bounds__(256)
void gemm_kernel(const float* __restrict__ A, const float* __restrict__ Bm,
                 float* __restrict__ C, int M, int N, int Kd,
                 const float* __restrict__ bias,
                 const float* __restrict__ rowv, const float* __restrict__ colv)
{
    __shared__ float As[2][8][128];
    __shared__ float Bs[2][8][128];

    const int tid = threadIdx.x;
    const int bm = blockIdx.y * 128;
    const int bn = blockIdx.x * 128;
    const int tr = (tid / 16) * 8;   // row offset of this thread's 8x8
    const int tc = (tid % 16) * 8;   // col offset

    float acc[8][8];
    #pragma unroll
    for (int i = 0; i < 8; i++)
        #pragma unroll
        for (int j = 0; j < 8; j++) acc[i][j] = 0.f;

    const int lr  = tid >> 1;          // 0..127  row within tile for A/NT-B loads
    const int lc4 = (tid & 1) * 4;     // 0 or 4  k-offset (float4)
    const int bkr = tid >> 5;          // 0..7    k-row for NN-B load
    const int bc4 = (tid & 31) * 4;    // 0..124  col offset (float4)

    // Per-thread gmem source pointers (advance by 8 columns / 8 rows per step)
    const float* pA = A + (size_t)(bm + lr) * Kd + lc4;
    const float* pB = TRANSB ? (Bm + (size_t)(bn + lr) * Kd + lc4)
                             : (Bm + (size_t)bkr * N + bn + bc4);
    const size_t stepB = TRANSB ? 8 : (size_t)8 * N;

    // ---- prologue: tile 0 -> smem[0] ----
    {
        float4 av = *(const float4*)pA;
        As[0][lc4 + 0][lr] = av.x;
        As[0][lc4 + 1][lr] = av.y;
        As[0][lc4 + 2][lr] = av.z;
        As[0][lc4 + 3][lr] = av.w;
        float4 bv = *(const float4*)pB;
        if (TRANSB) {
            Bs[0][lc4 + 0][lr] = bv.x;
            Bs[0][lc4 + 1][lr] = bv.y;
            Bs[0][lc4 + 2][lr] = bv.z;
            Bs[0][lc4 + 3][lr] = bv.w;
        } else {
            *(float4*)&Bs[0][bkr][bc4] = bv;
        }
    }
    __syncthreads();

    int cur = 0;
    const int nSteps = Kd / 8;
    for (int step = 0; step < nSteps; step++) {
        // ---- issue gmem loads for next tile into registers ----
        float4 av, bv;
        const bool hasNext = (step + 1) < nSteps;
        if (hasNext) {
            av = *(const float4*)(pA + (size_t)(step + 1) * 8);
            bv = *(const float4*)(pB + (size_t)(step + 1) * stepB);
        }

        // ---- compute from smem[cur] ----
        #pragma unroll
        for (int kk = 0; kk < 8; kk++) {
            float4 a0 = *(float4*)&As[cur][kk][tr];
            float4 a1 = *(float4*)&As[cur][kk][tr + 4];
            float4 b0 = *(float4*)&Bs[cur][kk][tc];
            float4 b1 = *(float4*)&Bs[cur][kk][tc + 4];
            float a[8] = {a0.x, a0.y, a0.z, a0.w, a1.x, a1.y, a1.z, a1.w};
            float b[8] = {b0.x, b0.y, b0.z, b0.w, b1.x, b1.y, b1.z, b1.w};
            #pragma unroll
            for (int i = 0; i < 8; i++)
                #pragma unroll
                for (int j = 0; j < 8; j++)
                    acc[i][j] = fmaf(a[i], b[j], acc[i][j]);
        }

        // ---- store next tile into the other buffer ----
        if (hasNext) {
            int nxt = cur ^ 1;
            As[nxt][lc4 + 0][lr] = av.x;
            As[nxt][lc4 + 1][lr] = av.y;
            As[nxt][lc4 + 2][lr] = av.z;
            As[nxt][lc4 + 3][lr] = av.w;
            if (TRANSB) {
                Bs[nxt][lc4 + 0][lr] = bv.x;
                Bs[nxt][lc4 + 1][lr] = bv.y;
                Bs[nxt][lc4 + 2][lr] = bv.z;
                Bs[nxt][lc4 + 3][lr] = bv.w;
            } else {
                *(float4*)&Bs[nxt][bkr][bc4] = bv;
            }
            __syncthreads();
            cur = nxt;
        }
    }

    #pragma unroll
    for (int i = 0; i < 8; i++) {
        int row = bm + tr + i;
        float rv = (EPI == 3) ? rowv[row] : 0.f;
        #pragma unroll
        for (int j = 0; j < 8; j++) {
            int col = bn + tc + j;
            float v = acc[i][j];
            if (EPI == 1)      v = v + bias[col];
            else if (EPI == 2) v = fmaxf(v + bias[col], 0.f);
            else if (EPI == 3) v = sqrtf(fmaxf(rv + colv[col] - 2.f * v, 0.f));
            C[(size_t)row * N + col] = v;
        }
    }
}

// ---------------------------------------------------------------------------
// Score normalization: in-place on diff rows of length KV.
// s = exp(-10*diff / rowmax(diff));  s /= rowsum(s)
// One block (256 threads) per row; row staged in smem (16 KB).
// ---------------------------------------------------------------------------
__global__ __launch_bounds__(256)
void score_kernel(float* __restrict__ buf)
{
    __shared__ float sm[KV];
    __shared__ float red[256];
    const int row = blockIdx.x;
    float* p = buf + (size_t)row * KV;

    float m = 0.f;  // diff >= 0
    for (int i = threadIdx.x; i < KV; i += 256) {
        float v = p[i];
        sm[i] = v;
        m = fmaxf(m, v);
    }
    red[threadIdx.x] = m;
    __syncthreads();
    for (int s = 128; s > 0; s >>= 1) {
        if (threadIdx.x < s) red[threadIdx.x] = fmaxf(red[threadIdx.x], red[threadIdx.x + s]);
        __syncthreads();
    }
    m = red[0];
    __syncthreads();

    const float scale = -10.f / m;
    float sum = 0.f;
    for (int i = threadIdx.x; i < KV; i += 256) {
        float e = expf(sm[i] * scale);
        sm[i] = e;
        sum += e;
    }
    red[threadIdx.x] = sum;
    __syncthreads();
    for (int s = 128; s > 0; s >>= 1) {
        if (threadIdx.x < s) red[threadIdx.x] += red[threadIdx.x + s];
        __syncthreads();
    }
    const float inv = 1.f / red[0];
    for (int i = threadIdx.x; i < KV; i += 256) p[i] = sm[i] * inv;
}

// ---------------------------------------------------------------------------
// Row softmax in place (rows of length KV).
// ---------------------------------------------------------------------------
__global__ __launch_bounds__(256)
void softmax_kernel(float* __restrict__ buf)
{
    __shared__ float sm[KV];
    __shared__ float red[256];
    const int row = blockIdx.x;
    float* p = buf + (size_t)row * KV;

    float m = -CUDART_INF_F;
    for (int i = threadIdx.x; i < KV; i += 256) {
        float v = p[i];
        sm[i] = v;
        m = fmaxf(m, v);
    }
    red[threadIdx.x] = m;
    __syncthreads();
    for (int s = 128; s > 0; s >>= 1) {
        if (threadIdx.x < s) red[threadIdx.x] = fmaxf(red[threadIdx.x], red[threadIdx.x + s]);
        __syncthreads();
    }
    m = red[0];
    __syncthreads();

    float sum = 0.f;
    for (int i = threadIdx.x; i < KV; i += 256) {
        float e = expf(sm[i] - m);
        sm[i] = e;
        sum += e;
    }
    red[threadIdx.x] = sum;
    __syncthreads();
    for (int s = 128; s > 0; s >>= 1) {
        if (threadIdx.x < s) red[threadIdx.x] += red[threadIdx.x + s];
        __syncthreads();
    }
    const float inv = 1.f / red[0];
    for (int i = threadIdx.x; i < KV; i += 256) p[i] = sm[i] * inv;
}

// ---------------------------------------------------------------------------
// out[B,V] = att[B,K] @ values[K,V], V = 64.
// Block handles 64 rows; threads (64,4); each thread does 16 rows x 1 col.
// ---------------------------------------------------------------------------
__global__ __launch_bounds__(256)
void att_values_kernel(const float* __restrict__ att,
                       const float* __restrict__ values,
                       float* __restrict__ out)
{
    __shared__ float vs[64][65];
    __shared__ float as_[64][65];
    const int tx = threadIdx.x;   // 0..63 : output col / k lane
    const int ty = threadIdx.y;   // 0..3
    const int r0 = blockIdx.x * 64;

    float acc[16];
    #pragma unroll
    for (int r = 0; r < 16; r++) acc[r] = 0.f;

    for (int k0 = 0; k0 < KV; k0 += 64) {
        #pragma unroll
        for (int i = 0; i < 16; i++) {
            int kk = ty * 16 + i;
            vs[kk][tx]  = values[(size_t)(k0 + kk) * VV + tx];
            as_[kk][tx] = att[(size_t)(r0 + kk) * KV + k0 + tx];
        }
        __syncthreads();
        #pragma unroll 8
        for (int kk = 0; kk < 64; kk++) {
            float v = vs[kk][tx];
            #pragma unroll
            for (int r = 0; r < 16; r++)
                acc[r] = fmaf(as_[ty * 16 + r][kk], v, acc[r]);
        }
        __syncthreads();
    }
    #pragma unroll
    for (int r = 0; r < 16; r++)
        out[(size_t)(r0 + ty * 16 + r) * VV + tx] = acc[r];
}

// ---------------------------------------------------------------------------
// Launch: full pipeline, graph-capturable (kernel launches only).
// Input order: x, keys, values, W_embed, b_embed, W_hidden, b_hidden, W_att, b_att
// ---------------------------------------------------------------------------
extern "C" void kernel_launch(void* const* d_in, const int* in_sizes, int n_in,
                              void* d_out, int out_size)
{
    const float* x        = (const float*)d_in[0];
    const float* keys     = (const float*)d_in[1];
    const float* values   = (const float*)d_in[2];
    const float* W_embed  = (const float*)d_in[3];
    const float* b_embed  = (const float*)d_in[4];
    const float* W_hidden = (const float*)d_in[5];
    const float* b_hidden = (const float*)d_in[6];
    const float* W_att    = (const float*)d_in[7];
    const float* b_att    = (const float*)d_in[8];
    float* out = (float*)d_out;

    float *s, *e, *h, *l, *x2, *k2;
    cudaGetSymbolAddress((void**)&s,  g_s);
    cudaGetSymbolAddress((void**)&e,  g_e);
    cudaGetSymbolAddress((void**)&h,  g_h);
    cudaGetSymbolAddress((void**)&l,  g_l);
    cudaGetSymbolAddress((void**)&x2, g_x2);
    cudaGetSymbolAddress((void**)&k2, g_k2);

    // 1. row norms
    rownorm2_kernel<<<BB, 128>>>(x, x2);
    rownorm2_kernel<<<KV, 128>>>(keys, k2);

    // 2. diff = sqrt(max(x2 + k2 - 2 x.keys^T, 0))   [B,K]
    gemm_kernel<3, true><<<dim3(KV / 128, BB / 128), 256>>>(
        x, keys, s, BB, KV, DD, nullptr, x2, k2);

    // 3. score normalization (in place)
    score_kernel<<<BB, 256>>>(s);

    // 4. e = relu(s @ W_embed + b)   [B,E]
    gemm_kernel<2, false><<<dim3(EE / 128, BB / 128), 256>>>(
        s, W_embed, e, BB, EE, KV, b_embed, nullptr, nullptr);

    // 5. h = relu(e @ W_hidden + b)  [B,H]
    gemm_kernel<2, false><<<dim3(HH / 128, BB / 128), 256>>>(
        e, W_hidden, h, BB, HH, EE, b_hidden, nullptr, nullptr);

    // 6. logits = h @ W_att + b      [B,K]
    gemm_kernel<1, false><<<dim3(KV / 128, BB / 128), 256>>>(
        h, W_att, l, BB, KV, HH, b_att, nullptr, nullptr);

    // 7. att = softmax(logits) in place
    softmax_kernel<<<BB, 256>>>(l);

    // 8. out = att @ values          [B,V]
    att_values_kernel<<<BB / 64, dim3(64, 4)>>>(l, values, out);
}

// round 9
// speedup vs baseline: 4.1956x; 4.1956x over previous
#include <cuda_runtime.h>
#include <cuda_bf16.h>
#include <math_constants.h>
#include <cstdint>

// Problem dims (fixed by the dataset)
#define BB 4096   // batch
#define DD 128    // feature dim
#define KV 4096   // num keys
#define EE 1024   // embed
#define HH 2048   // hidden
#define VV 64     // value dim

// ---------------------------------------------------------------------------
// Scratch (device globals -- no allocation allowed anywhere)
// ---------------------------------------------------------------------------
__device__ float    g_diff[(size_t)BB * KV];  // distance              (64 MB)
__device__ float    g_l[(size_t)BB * KV];     // logits -> att         (64 MB)
__device__ uint16_t g_sb[(size_t)BB * KV];    // score bf16            (32 MB)
__device__ uint16_t g_eb[(size_t)BB * EE];    // embed bf16            ( 8 MB)
__device__ uint16_t g_hb[(size_t)BB * HH];    // hidden bf16           (16 MB)
__device__ uint16_t g_xb[(size_t)BB * DD];    // x bf16
__device__ uint16_t g_kb[(size_t)KV * DD];    // keys bf16
__device__ uint16_t g_WeT[(size_t)EE * KV];   // W_embed^T bf16        ( 8 MB)
__device__ uint16_t g_WhT[(size_t)HH * EE];   // W_hidden^T bf16       ( 4 MB)
__device__ uint16_t g_WaT[(size_t)KV * HH];   // W_att^T bf16          (16 MB)
__device__ float    g_x2[BB];
__device__ float    g_k2[KV];

// ---------------------------------------------------------------------------
// Helpers
// ---------------------------------------------------------------------------
__device__ __forceinline__ uint32_t smem_u32(const void* p) {
    uint32_t a;
    asm("{ .reg .u64 t; cvta.to.shared.u64 t, %1; cvt.u32.u64 %0, t; }" : "=r"(a) : "l"(p));
    return a;
}

#define CP_ASYNC16(dst_u32, src_ptr) \
    asm volatile("cp.async.cg.shared.global [%0], [%1], 16;" :: "r"(dst_u32), "l"(src_ptr))
#define CP_COMMIT() asm volatile("cp.async.commit_group;" ::: "memory")
#define CP_WAIT1()  asm volatile("cp.async.wait_group 1;" ::: "memory")
#define CP_WAIT0()  asm volatile("cp.async.wait_group 0;" ::: "memory")

#define LDSM_X4(r0, r1, r2, r3, addr) \
    asm volatile("ldmatrix.sync.aligned.m8n8.x4.shared.b16 {%0,%1,%2,%3}, [%4];" \
                 : "=r"(r0), "=r"(r1), "=r"(r2), "=r"(r3) : "r"(addr))
#define LDSM_X2(r0, r1, addr) \
    asm volatile("ldmatrix.sync.aligned.m8n8.x2.shared.b16 {%0,%1}, [%2];" \
                 : "=r"(r0), "=r"(r1) : "r"(addr))

#define MMA_BF16(c, a, b) \
    asm volatile("mma.sync.aligned.m16n8k16.row.col.f32.bf16.bf16.f32 " \
                 "{%0,%1,%2,%3}, {%4,%5,%6,%7}, {%8,%9}, {%0,%1,%2,%3};" \
                 : "+f"((c)[0]), "+f"((c)[1]), "+f"((c)[2]), "+f"((c)[3]) \
                 : "r"((a)[0]), "r"((a)[1]), "r"((a)[2]), "r"((a)[3]), \
                   "r"((b)[0]), "r"((b)[1]))

// ---------------------------------------------------------------------------
// HMMA bf16 GEMM: C[M,Ntot] (epi) = A[M,Kd] x Bt[Ntot,Kd]^T
// CTA tile 128x128, BK=32, 256 threads (8 warps, 2x4), warp tile 64x32.
// cp.async double-buffered smem; rows padded to 40 bf16 (80B) for
// conflict-free ldmatrix. EPI: 1=+bias(f32), 2=relu(+bias)(bf16),
// 3=dist sqrt(max(rv+cv-2acc,0))(f32).
// M, Ntot multiples of 128; Kd multiple of 32.
// ---------------------------------------------------------------------------
#define ROWB 80              // bytes per smem row (40 bf16)
#define TILEB (128 * ROWB)   // 10240 B per tile buffer

template<int EPI>
__global__ __launch_bounds__(256)
void mma_gemm(const uint16_t* __restrict__ A, const uint16_t* __restrict__ Bt,
              void* __restrict__ Cout, int Kd, int Ntot,
              const float* __restrict__ bias,
              const float* __restrict__ rowv, const float* __restrict__ colv)
{
    __shared__ __align__(16) uint8_t sA[2 * TILEB];
    __shared__ __align__(16) uint8_t sB[2 * TILEB];

    const int tid  = threadIdx.x;
    const int wid  = tid >> 5;
    const int lane = tid & 31;
    const int wm   = wid >> 2;   // 0..1
    const int wn   = wid & 3;    // 0..3
    const int bm   = blockIdx.y * 128;
    const int bn   = blockIdx.x * 128;

    const uint32_t aA = smem_u32(sA);
    const uint32_t aB = smem_u32(sB);

    // ---- global load geometry: thread covers rows lr and lr+64, quad lq ----
    const int lr = tid >> 2;     // 0..63
    const int lq = tid & 3;      // 0..3 (16B quad within 64B of k-chunk)
    const uint16_t* gA = A + (size_t)(bm + lr) * Kd + lq * 8;
    const uint16_t* gB = Bt + (size_t)(bn + lr) * Kd + lq * 8;
    const size_t rstep = (size_t)64 * Kd;
    const uint32_t st0 = lr * ROWB + lq * 16;          // smem byte offset row lr
    const uint32_t st1 = (lr + 64) * ROWB + lq * 16;   // row lr+64

    #define LOAD_TILE(c, buf) do { \
        const size_t kc = (size_t)(c) * 32; \
        const uint32_t o = (buf) * TILEB; \
        CP_ASYNC16(aA + o + st0, gA + kc); \
        CP_ASYNC16(aA + o + st1, gA + rstep + kc); \
        CP_ASYNC16(aB + o + st0, gB + kc); \
        CP_ASYNC16(aB + o + st1, gB + rstep + kc); \
        CP_COMMIT(); \
    } while (0)

    // ---- ldmatrix base offsets (bytes, within one tile buffer) ----
    // A: row = wm*64 + (lane&15) [+ mt*16], kbyte = ks*32 + ((lane>=16)?16:0)
    const uint32_t aoff = (uint32_t)(wm * 64 + (lane & 15)) * ROWB + ((lane >> 4) << 4);
    // B: row = wn*32 + (lane&7) [+ nt*8], kbyte = ks*32 + (((lane>>3)&1)?16:0)
    const uint32_t boff = (uint32_t)(wn * 32 + (lane & 7)) * ROWB + (((lane >> 3) & 1) << 4);

    float acc[4][4][4];
    #pragma unroll
    for (int i = 0; i < 4; i++)
        #pragma unroll
        for (int j = 0; j < 4; j++)
            #pragma unroll
            for (int v = 0; v < 4; v++) acc[i][j][v] = 0.f;

    const int nIter = Kd >> 5;

    LOAD_TILE(0, 0);

    for (int c = 0; c < nIter; c++) {
        const int buf = c & 1;
        if (c + 1 < nIter) {
            LOAD_TILE(c + 1, buf ^ 1);
            CP_WAIT1();
        } else {
            CP_WAIT0();
        }
        __syncthreads();

        const uint32_t baseA = aA + buf * TILEB + aoff;
        const uint32_t baseB = aB + buf * TILEB + boff;
        #pragma unroll
        for (int ks = 0; ks < 2; ks++) {
            uint32_t afr[4][4], bfr[4][2];
            #pragma unroll
            for (int mt = 0; mt < 4; mt++)
                LDSM_X4(afr[mt][0], afr[mt][1], afr[mt][2], afr[mt][3],
                        baseA + mt * (16 * ROWB) + ks * 32);
            #pragma unroll
            for (int nt = 0; nt < 4; nt++)
                LDSM_X2(bfr[nt][0], bfr[nt][1],
                        baseB + nt * (8 * ROWB) + ks * 32);
            #pragma unroll
            for (int mt = 0; mt < 4; mt++)
                #pragma unroll
                for (int nt = 0; nt < 4; nt++)
                    MMA_BF16(acc[mt][nt], afr[mt], bfr[nt]);
        }
        __syncthreads();
    }

    // ---- epilogue ----
    const int tm = lane >> 2;        // 0..7
    const int tn = (lane & 3) * 2;   // 0,2,4,6

    // Per-thread column params (4 nt-tiles x 2 cols), loaded once.
    float cb0[4], cb1[4];
    {
        const float* src = (EPI == 3) ? colv : bias;
        #pragma unroll
        for (int nt = 0; nt < 4; nt++) {
            const int n0 = bn + wn * 32 + nt * 8 + tn;
            cb0[nt] = __ldg(src + n0);
            cb1[nt] = __ldg(src + n0 + 1);
        }
    }

    #pragma unroll
    for (int mt = 0; mt < 4; mt++) {
        const int m0 = bm + wm * 64 + mt * 16 + tm;   // rows m0 and m0+8
        float rv0 = 0.f, rv1 = 0.f;
        if (EPI == 3) { rv0 = __ldg(rowv + m0); rv1 = __ldg(rowv + m0 + 8); }
        #pragma unroll
        for (int nt = 0; nt < 4; nt++) {
            const int n0 = bn + wn * 32 + nt * 8 + tn;
            const float* cc = acc[mt][nt];
            if (EPI == 1) {
                float* C = (float*)Cout;
                *(float2*)(C + (size_t)m0 * Ntot + n0) = make_float2(cc[0] + cb0[nt], cc[1] + cb1[nt]);
                *(float2*)(C + (size_t)(m0 + 8) * Ntot + n0) = make_float2(cc[2] + cb0[nt], cc[3] + cb1[nt]);
            } else if (EPI == 2) {
                uint16_t* C = (uint16_t*)Cout;
                __nv_bfloat162 p0 = __floats2bfloat162_rn(fmaxf(cc[0] + cb0[nt], 0.f), fmaxf(cc[1] + cb1[nt], 0.f));
                __nv_bfloat162 p1 = __floats2bfloat162_rn(fmaxf(cc[2] + cb0[nt], 0.f), fmaxf(cc[3] + cb1[nt], 0.f));
                *(uint32_t*)(C + (size_t)m0 * Ntot + n0) = *(uint32_t*)&p0;
                *(uint32_t*)(C + (size_t)(m0 + 8) * Ntot + n0) = *(uint32_t*)&p1;
            } else { // EPI == 3
                float* C = (float*)Cout;
                *(float2*)(C + (size_t)m0 * Ntot + n0) = make_float2(
                    sqrtf(fmaxf(rv0 + cb0[nt] - 2.f * cc[0], 0.f)),
                    sqrtf(fmaxf(rv0 + cb1[nt] - 2.f * cc[1], 0.f)));
                *(float2*)(C + (size_t)(m0 + 8) * Ntot + n0) = make_float2(
                    sqrtf(fmaxf(rv1 + cb0[nt] - 2.f * cc[2], 0.f)),
                    sqrtf(fmaxf(rv1 + cb1[nt] - 2.f * cc[3], 0.f)));
            }
        }
    }
    #undef LOAD_TILE
}

// ---------------------------------------------------------------------------
// fp32 -> bf16 elementwise convert
// ---------------------------------------------------------------------------
__global__ void conv_f2b(const float* __restrict__ in, uint16_t* __restrict__ out, int n)
{
    int i = blockIdx.x * blockDim.x + threadIdx.x;
    if (i < n) {
        __nv_bfloat16 b = __float2bfloat16(in[i]);
        out[i] = *(uint16_t*)&b;
    }
}

// ---------------------------------------------------------------------------
// Transpose fp32 [R,C] -> bf16 [C,R].  R, C multiples of 32.  block (32,8).
// ---------------------------------------------------------------------------
__global__ void transpose_f2b(const float* __restrict__ in, uint16_t* __restrict__ out,
                              int R, int C)
{
    __shared__ float t[32][33];
    const int bx = blockIdx.x * 32;  // col-tile in input
    const int by = blockIdx.y * 32;  // row-tile in input
    #pragma unroll
    for (int i = 0; i < 32; i += 8)
        t[threadIdx.y + i][threadIdx.x] = in[(size_t)(by + threadIdx.y + i) * C + bx + threadIdx.x];
    __syncthreads();
    #pragma unroll
    for (int i = 0; i < 32; i += 8) {
        __nv_bfloat16 b = __float2bfloat16(t[threadIdx.x][threadIdx.y + i]);
        out[(size_t)(bx + threadIdx.y + i) * R + by + threadIdx.x] = *(uint16_t*)&b;
    }
}

// ---------------------------------------------------------------------------
// Row squared-norm: one block (128 threads) per row, D = 128
// ---------------------------------------------------------------------------
__global__ void rownorm2_kernel(const float* __restrict__ X, float* __restrict__ out)
{
    int row = blockIdx.x;
    float v = X[(size_t)row * DD + threadIdx.x];
    float s = v * v;
    #pragma unroll
    for (int o = 16; o > 0; o >>= 1) s += __shfl_down_sync(0xffffffffu, s, o);
    __shared__ float ws[4];
    if ((threadIdx.x & 31) == 0) ws[threadIdx.x >> 5] = s;
    __syncthreads();
    if (threadIdx.x == 0) out[row] = ws[0] + ws[1] + ws[2] + ws[3];
}

// ---------------------------------------------------------------------------
// Score: reads fp32 diff row, writes normalized bf16 score row.
// s = exp(-10*diff / rowmax(diff));  s /= rowsum(s)
// ---------------------------------------------------------------------------
__global__ __launch_bounds__(256)
void score_kernel(const float* __restrict__ diff, uint16_t* __restrict__ outb)
{
    __shared__ float sm[KV];
    __shared__ float red[256];
    const int row = blockIdx.x;
    const float* p = diff + (size_t)row * KV;
    uint16_t* o = outb + (size_t)row * KV;

    float m = 0.f;
    for (int i = threadIdx.x; i < KV; i += 256) {
        float v = p[i];
        sm[i] = v;
        m = fmaxf(m, v);
    }
    red[threadIdx.x] = m;
    __syncthreads();
    for (int s = 128; s > 0; s >>= 1) {
        if (threadIdx.x < s) red[threadIdx.x] = fmaxf(red[threadIdx.x], red[threadIdx.x + s]);
        __syncthreads();
    }
    m = red[0];
    __syncthreads();

    const float scale = -10.f / m;
    float sum = 0.f;
    for (int i = threadIdx.x; i < KV; i += 256) {
        float e = expf(sm[i] * scale);
        sm[i] = e;
        sum += e;
    }
    red[threadIdx.x] = sum;
    __syncthreads();
    for (int s = 128; s > 0; s >>= 1) {
        if (threadIdx.x < s) red[threadIdx.x] += red[threadIdx.x + s];
        __syncthreads();
    }
    const float inv = 1.f / red[0];
    for (int i = threadIdx.x; i < KV; i += 256) {
        __nv_bfloat16 b = __float2bfloat16(sm[i] * inv);
        o[i] = *(uint16_t*)&b;
    }
}

// ---------------------------------------------------------------------------
// Row softmax in place (rows of length KV), fp32.
// ---------------------------------------------------------------------------
__global__ __launch_bounds__(256)
void softmax_kernel(float* __restrict__ buf)
{
    __shared__ float sm[KV];
    __shared__ float red[256];
    const int row = blockIdx.x;
    float* p = buf + (size_t)row * KV;

    float m = -CUDART_INF_F;
    for (int i = threadIdx.x; i < KV; i += 256) {
        float v = p[i];
        sm[i] = v;
        m = fmaxf(m, v);
    }
    red[threadIdx.x] = m;
    __syncthreads();
    for (int s = 128; s > 0; s >>= 1) {
        if (threadIdx.x < s) red[threadIdx.x] = fmaxf(red[threadIdx.x], red[threadIdx.x + s]);
        __syncthreads();
    }
    m = red[0];
    __syncthreads();

    float sum = 0.f;
    for (int i = threadIdx.x; i < KV; i += 256) {
        float e = expf(sm[i] - m);
        sm[i] = e;
        sum += e;
    }
    red[threadIdx.x] = sum;
    __syncthreads();
    for (int s = 128; s > 0; s >>= 1) {
        if (threadIdx.x < s) red[threadIdx.x] += red[threadIdx.x + s];
        __syncthreads();
    }
    const float inv = 1.f / red[0];
    for (int i = threadIdx.x; i < KV; i += 256) p[i] = sm[i] * inv;
}

// ---------------------------------------------------------------------------
// out[B,V] = att[B,K] @ values[K,V], V = 64 (fp32, exact).
// ---------------------------------------------------------------------------
__global__ __launch_bounds__(256)
void att_values_kernel(const float* __restrict__ att,
                       const float* __restrict__ values,
                       float* __restrict__ out)
{
    __shared__ float vs[64][65];
    __shared__ float as_[64][65];
    const int tx = threadIdx.x;
    const int ty = threadIdx.y;
    const int r0 = blockIdx.x * 64;

    float acc[16];
    #pragma unroll
    for (int r = 0; r < 16; r++) acc[r] = 0.f;

    for (int k0 = 0; k0 < KV; k0 += 64) {
        #pragma unroll
        for (int i = 0; i < 16; i++) {
            int kk = ty * 16 + i;
            vs[kk][tx]  = values[(size_t)(k0 + kk) * VV + tx];
            as_[kk][tx] = att[(size_t)(r0 + kk) * KV + k0 + tx];
        }
        __syncthreads();
        #pragma unroll 8
        for (int kk = 0; kk < 64; kk++) {
            float v = vs[kk][tx];
            #pragma unroll
            for (int r = 0; r < 16; r++)
                acc[r] = fmaf(as_[ty * 16 + r][kk], v, acc[r]);
        }
        __syncthreads();
    }
    #pragma unroll
    for (int r = 0; r < 16; r++)
        out[(size_t)(r0 + ty * 16 + r) * VV + tx] = acc[r];
}

// ---------------------------------------------------------------------------
// Launch: full pipeline, graph-capturable (kernel launches only).
// Inputs: x, keys, values, W_embed, b_embed, W_hidden, b_hidden, W_att, b_att
// ---------------------------------------------------------------------------
extern "C" void kernel_launch(void* const* d_in, const int* in_sizes, int n_in,
                              void* d_out, int out_size)
{
    const float* x        = (const float*)d_in[0];
    const float* keys     = (const float*)d_in[1];
    const float* values   = (const float*)d_in[2];
    const float* W_embed  = (const float*)d_in[3];
    const float* b_embed  = (const float*)d_in[4];
    const float* W_hidden = (const float*)d_in[5];
    const float* b_hidden = (const float*)d_in[6];
    const float* W_att    = (const float*)d_in[7];
    const float* b_att    = (const float*)d_in[8];
    float* out = (float*)d_out;

    float *diff, *l, *x2, *k2;
    uint16_t *sb, *eb, *hb, *xb, *kb, *WeT, *WhT, *WaT;
    cudaGetSymbolAddress((void**)&diff, g_diff);
    cudaGetSymbolAddress((void**)&l,    g_l);
    cudaGetSymbolAddress((void**)&sb,   g_sb);
    cudaGetSymbolAddress((void**)&eb,   g_eb);
    cudaGetSymbolAddress((void**)&hb,   g_hb);
    cudaGetSymbolAddress((void**)&xb,   g_xb);
    cudaGetSymbolAddress((void**)&kb,   g_kb);
    cudaGetSymbolAddress((void**)&WeT,  g_WeT);
    cudaGetSymbolAddress((void**)&WhT,  g_WhT);
    cudaGetSymbolAddress((void**)&WaT,  g_WaT);
    cudaGetSymbolAddress((void**)&x2,   g_x2);
    cudaGetSymbolAddress((void**)&k2,   g_k2);

    // 0. conversions / transposes (graph nodes; cheap)
    conv_f2b<<<(BB * DD + 255) / 256, 256>>>(x, xb, BB * DD);
    conv_f2b<<<(KV * DD + 255) / 256, 256>>>(keys, kb, KV * DD);
    transpose_f2b<<<dim3(EE / 32, KV / 32), dim3(32, 8)>>>(W_embed, WeT, KV, EE);
    transpose_f2b<<<dim3(HH / 32, EE / 32), dim3(32, 8)>>>(W_hidden, WhT, EE, HH);
    transpose_f2b<<<dim3(KV / 32, HH / 32), dim3(32, 8)>>>(W_att, WaT, HH, KV);

    // 1. row norms (fp32, exact)
    rownorm2_kernel<<<BB, 128>>>(x, x2);
    rownorm2_kernel<<<KV, 128>>>(keys, k2);

    // 2. diff = sqrt(max(x2 + k2 - 2 x.keys^T, 0))   [B,K]   (HMMA bf16)
    mma_gemm<3><<<dim3(KV / 128, BB / 128), 256>>>(xb, kb, diff, DD, KV,
                                                   nullptr, x2, k2);

    // 3. score normalization -> bf16
    score_kernel<<<BB, 256>>>(diff, sb);

    // 4. e = relu(s @ W_embed + b)   [B,E] bf16
    mma_gemm<2><<<dim3(EE / 128, BB / 128), 256>>>(sb, WeT, eb, KV, EE,
                                                   b_embed, nullptr, nullptr);

    // 5. h = relu(e @ W_hidden + b)  [B,H] bf16
    mma_gemm<2><<<dim3(HH / 128, BB / 128), 256>>>(eb, WhT, hb, EE, HH,
                                                   b_hidden, nullptr, nullptr);

    // 6. logits = h @ W_att + b      [B,K] fp32
    mma_gemm<1><<<dim3(KV / 128, BB / 128), 256>>>(hb, WaT, l, HH, KV,
                                                   b_att, nullptr, nullptr);

    // 7. att = softmax(logits) in place
    softmax_kernel<<<BB, 256>>>(l);

    // 8. out = att @ values (fp32)
    att_values_kernel<<<BB / 64, dim3(64, 4)>>>(l, values, out);
}